// round 14
// baseline (speedup 1.0000x reference)
#include <cuda_runtime.h>
#include <cuda_fp16.h>
#include <cstdint>
#include <math.h>

// Problem constants
constexpr int CB  = 32;
constexpr int CN  = 512;
constexpr int CD  = 1024;
constexpr int CH  = 8;
constexpr int CHD = 128;
constexpr int C3D = 3 * CD;
constexpr int CM  = CB * CN;   // 16384

// ---------------- scratch (device globals) ----------------------------------
__device__ __half g_vt[(size_t)CM * C3D];
__device__ __half g_qt[(size_t)CM * C3D];
__device__ __half g_vh[(size_t)CM * CD],  g_qh[(size_t)CM * CD];
__device__ __half g_vu[(size_t)CM * CD],  g_qu[(size_t)CM * CD];
__device__ __half g_Wvt[(size_t)C3D * CD],     g_Wqt[(size_t)C3D * CD];
__device__ __half g_Wvot[(size_t)CD * 2 * CD], g_Wqot[(size_t)CD * 2 * CD];

// ---------------- base-ISA PTX helpers ---------------------------------------
__device__ __forceinline__ uint32_t smem_u32(const void* p) {
    uint32_t a;
    asm("{ .reg .u64 t; cvta.to.shared.u64 t, %1; cvt.u32.u64 %0, t; }" : "=r"(a) : "l"(p));
    return a;
}
__device__ __forceinline__ void cp_async16(uint32_t dst, const void* src) {
    asm volatile("cp.async.cg.shared.global [%0], [%1], 16;" :: "r"(dst), "l"(src) : "memory");
}
__device__ __forceinline__ void cp_commit() { asm volatile("cp.async.commit_group;" ::: "memory"); }
template <int N>
__device__ __forceinline__ void cp_wait() { asm volatile("cp.async.wait_group %0;" :: "n"(N) : "memory"); }

__device__ __forceinline__ void ldm_x4(uint32_t* r, uint32_t addr) {
    asm volatile("ldmatrix.sync.aligned.m8n8.x4.shared.b16 {%0,%1,%2,%3}, [%4];"
        : "=r"(r[0]), "=r"(r[1]), "=r"(r[2]), "=r"(r[3]) : "r"(addr));
}
__device__ __forceinline__ void ldm_x4_trans(uint32_t* r, uint32_t addr) {
    asm volatile("ldmatrix.sync.aligned.m8n8.x4.trans.shared.b16 {%0,%1,%2,%3}, [%4];"
        : "=r"(r[0]), "=r"(r[1]), "=r"(r[2]), "=r"(r[3]) : "r"(addr));
}
__device__ __forceinline__ void mma_f16(float* c, const uint32_t* a, const uint32_t* b) {
    asm volatile("mma.sync.aligned.m16n8k16.row.col.f32.f16.f16.f32 "
        "{%0,%1,%2,%3}, {%4,%5,%6,%7}, {%8,%9}, {%0,%1,%2,%3};"
        : "+f"(c[0]), "+f"(c[1]), "+f"(c[2]), "+f"(c[3])
        : "r"(a[0]), "r"(a[1]), "r"(a[2]), "r"(a[3]), "r"(b[0]), "r"(b[1]));
}
__device__ __forceinline__ float fexp2(float x) {
    float y;
    asm("ex2.approx.ftz.f32 %0, %1;" : "=f"(y) : "f"(x));
    return y;
}

// Weight-GEMM tiling: CTA 256(M)x128(N), BK=64, 16 warps 4Mx4N (warp 64x32),
// 512 threads, 3-stage pipeline, 1 CTA/SM (16 warps/SM preserved).
constexpr int TSTR     = 72;
constexpr int ATILE_H  = 256 * TSTR;           // 18432 halves
constexpr int BTILE_H  = 128 * TSTR;           // 9216 halves
constexpr int STAGE_H  = ATILE_H + BTILE_H;    // 27648 halves
constexpr int GEMM_SMEM = 3 * STAGE_H * 2;     // 165888 B
constexpr float Q_PREMULT = 0.08838834764831845f * 1.4426950408889634f;

// =============================================================================
// stage-1 GEMM (merged v/q): C = fp16(relu(A @ W + bias)); query slice
// (cols [CD, 2CD)) pre-multiplied by scale*log2(e).
// =============================================================================
__global__ __launch_bounds__(512, 1)
void gemm_in(const __half* __restrict__ A0g, const __half* __restrict__ A1g,
             const __half* __restrict__ B0g, const __half* __restrict__ B1g,
             const float* __restrict__ bias0, const float* __restrict__ bias1,
             __half* __restrict__ C0g, __half* __restrict__ C1g,
             int M, int N, int K)
{
    extern __shared__ __half sm[];
    const uint32_t smb = smem_u32(sm);
    const int tid = threadIdx.x, wid = tid >> 5, lane = tid & 31;
    const int z = blockIdx.z;
    const __half* Ag = z ? A1g : A0g;
    const __half* Bg = z ? B1g : B0g;
    const float* bias = z ? bias1 : bias0;
    __half* Cg = z ? C1g : C0g;

    const int bm0 = blockIdx.y * 256, bn0 = blockIdx.x * 128;
    const int nk = K / 64;
    const int mw = (wid & 3) * 64, nw = (wid >> 2) * 32;

    auto load_stage = [&](int kc, int buf) {
        const int kk = kc * 64;
        const __half* a = Ag + (size_t)bm0 * K + kk;
        const __half* b = Bg + (size_t)bn0 * K + kk;
        const uint32_t base = smb + (uint32_t)buf * STAGE_H * 2;
        #pragma unroll
        for (int i = 0; i < 4; ++i) {                  // A: 256x64 = 2048 chunks
            const int idx = tid + i * 512;
            const int r = idx >> 3, c = (idx & 7) * 8;
            cp_async16(base + (uint32_t)(r * TSTR + c) * 2, a + (size_t)r * K + c);
        }
        #pragma unroll
        for (int i = 0; i < 2; ++i) {                  // B: 128x64 = 1024 chunks
            const int idx = tid + i * 512;
            const int r = idx >> 3, c = (idx & 7) * 8;
            cp_async16(base + ATILE_H * 2 + (uint32_t)(r * TSTR + c) * 2,
                       b + (size_t)r * K + c);
        }
        cp_commit();
    };

    float acc[4][4][4] = {};
    const int arow = lane & 15, acol = (lane >> 4) * 8;
    const int bq_row = (lane & 7) + ((lane >> 4) & 1) * 8;
    const int bq_col = ((lane >> 3) & 1) * 8;

    load_stage(0, 0);
    load_stage(1, 1);
    for (int kc = 0; kc < nk; ++kc) {
        const int buf = kc % 3;
        if (kc + 1 < nk) cp_wait<1>(); else cp_wait<0>();
        __syncthreads();
        if (kc + 2 < nk) load_stage(kc + 2, (kc + 2) % 3);
        const uint32_t base = smb + (uint32_t)buf * STAGE_H * 2;
        #pragma unroll
        for (int ks = 0; ks < 4; ++ks) {
            const int k0 = ks * 16;
            uint32_t bb[2][4];
            #pragma unroll
            for (int p = 0; p < 2; ++p) {
                const uint32_t boff =
                    (uint32_t)((nw + p * 16 + bq_row) * TSTR + k0 + bq_col) * 2;
                ldm_x4(bb[p], base + ATILE_H * 2 + boff);
            }
            #pragma unroll
            for (int mi = 0; mi < 4; ++mi) {
                uint32_t ah[4];
                const uint32_t aoff = (uint32_t)((mw + mi * 16 + arow) * TSTR + k0 + acol) * 2;
                ldm_x4(ah, base + aoff);
                #pragma unroll
                for (int p = 0; p < 2; ++p) {
                    mma_f16(acc[mi][2 * p],     ah, &bb[p][0]);
                    mma_f16(acc[mi][2 * p + 1], ah, &bb[p][2]);
                }
            }
        }
    }

    const int g = lane >> 2, tq = lane & 3;
    #pragma unroll
    for (int mi = 0; mi < 4; ++mi) {
        const int row0 = bm0 + mw + mi * 16 + g;
        #pragma unroll
        for (int ni = 0; ni < 4; ++ni) {
            const int col = bn0 + nw + ni * 8 + tq * 2;
            const float mult = (col >= CD && col < 2 * CD) ? Q_PREMULT : 1.0f;
            const float b0 = __ldg(&bias[col]), b1 = __ldg(&bias[col + 1]);
            *reinterpret_cast<__half2*>(&Cg[(size_t)row0 * N + col]) = __halves2half2(
                __float2half_rn(fmaxf(acc[mi][ni][0] + b0, 0.f) * mult),
                __float2half_rn(fmaxf(acc[mi][ni][1] + b1, 0.f) * mult));
            *reinterpret_cast<__half2*>(&Cg[(size_t)(row0 + 8) * N + col]) = __halves2half2(
                __float2half_rn(fmaxf(acc[mi][ni][2] + b0, 0.f) * mult),
                __float2half_rn(fmaxf(acc[mi][ni][3] + b1, 0.f) * mult));
        }
    }
}

// =============================================================================
// stage-5 GEMM (merged v/q): C = relu(concat(A0,A1) @ W + bias), fp32 out
// =============================================================================
__global__ __launch_bounds__(512, 1)
void gemm_out(const __half* __restrict__ A0v, const __half* __restrict__ A1v,
              const __half* __restrict__ A0q, const __half* __restrict__ A1q,
              int K0,
              const __half* __restrict__ Bv, const __half* __restrict__ Bq,
              const float* __restrict__ biasv, const float* __restrict__ biasq,
              float* __restrict__ C, size_t zoff,
              int M, int N, int K)
{
    extern __shared__ __half sm[];
    const uint32_t smb = smem_u32(sm);
    const int tid = threadIdx.x, wid = tid >> 5, lane = tid & 31;
    const int z = blockIdx.z;
    const __half* A0g = z ? A0q : A0v;
    const __half* A1g = z ? A1q : A1v;
    const __half* Bg  = z ? Bq  : Bv;
    const float* bias = z ? biasq : biasv;
    float* Cg = C + (size_t)z * zoff;

    const int bm0 = blockIdx.y * 256, bn0 = blockIdx.x * 128;
    const int nk = K / 64, K1 = K - K0;
    const int mw = (wid & 3) * 64, nw = (wid >> 2) * 32;

    auto load_stage = [&](int kc, int buf) {
        const int kk = kc * 64;
        const __half* a; int ldA, ka;
        if (kk < K0) { a = A0g; ldA = K0; ka = kk; }
        else         { a = A1g; ldA = K1; ka = kk - K0; }
        a += (size_t)bm0 * ldA + ka;
        const __half* b = Bg + (size_t)bn0 * K + kk;
        const uint32_t base = smb + (uint32_t)buf * STAGE_H * 2;
        #pragma unroll
        for (int i = 0; i < 4; ++i) {
            const int idx = tid + i * 512;
            const int r = idx >> 3, c = (idx & 7) * 8;
            cp_async16(base + (uint32_t)(r * TSTR + c) * 2, a + (size_t)r * ldA + c);
        }
        #pragma unroll
        for (int i = 0; i < 2; ++i) {
            const int idx = tid + i * 512;
            const int r = idx >> 3, c = (idx & 7) * 8;
            cp_async16(base + ATILE_H * 2 + (uint32_t)(r * TSTR + c) * 2,
                       b + (size_t)r * K + c);
        }
        cp_commit();
    };

    float acc[4][4][4] = {};
    const int arow = lane & 15, acol = (lane >> 4) * 8;
    const int bq_row = (lane & 7) + ((lane >> 4) & 1) * 8;
    const int bq_col = ((lane >> 3) & 1) * 8;

    load_stage(0, 0);
    load_stage(1, 1);
    for (int kc = 0; kc < nk; ++kc) {
        const int buf = kc % 3;
        if (kc + 1 < nk) cp_wait<1>(); else cp_wait<0>();
        __syncthreads();
        if (kc + 2 < nk) load_stage(kc + 2, (kc + 2) % 3);
        const uint32_t base = smb + (uint32_t)buf * STAGE_H * 2;
        #pragma unroll
        for (int ks = 0; ks < 4; ++ks) {
            const int k0 = ks * 16;
            uint32_t bb[2][4];
            #pragma unroll
            for (int p = 0; p < 2; ++p) {
                const uint32_t boff =
                    (uint32_t)((nw + p * 16 + bq_row) * TSTR + k0 + bq_col) * 2;
                ldm_x4(bb[p], base + ATILE_H * 2 + boff);
            }
            #pragma unroll
            for (int mi = 0; mi < 4; ++mi) {
                uint32_t ah[4];
                const uint32_t aoff = (uint32_t)((mw + mi * 16 + arow) * TSTR + k0 + acol) * 2;
                ldm_x4(ah, base + aoff);
                #pragma unroll
                for (int p = 0; p < 2; ++p) {
                    mma_f16(acc[mi][2 * p],     ah, &bb[p][0]);
                    mma_f16(acc[mi][2 * p + 1], ah, &bb[p][2]);
                }
            }
        }
    }

    const int g = lane >> 2, tq = lane & 3;
    #pragma unroll
    for (int mi = 0; mi < 4; ++mi) {
        const int row0 = bm0 + mw + mi * 16 + g;
        #pragma unroll
        for (int ni = 0; ni < 4; ++ni) {
            const int col = bn0 + nw + ni * 8 + tq * 2;
            const float b0 = __ldg(&bias[col]), b1 = __ldg(&bias[col + 1]);
            float2 o0, o1;
            o0.x = fmaxf(acc[mi][ni][0] + b0, 0.f);
            o0.y = fmaxf(acc[mi][ni][1] + b1, 0.f);
            o1.x = fmaxf(acc[mi][ni][2] + b0, 0.f);
            o1.y = fmaxf(acc[mi][ni][3] + b1, 0.f);
            *reinterpret_cast<float2*>(&Cg[(size_t)row0 * N + col]) = o0;
            *reinterpret_cast<float2*>(&Cg[(size_t)(row0 + 8) * N + col]) = o1;
        }
    }
}

// =============================================================================
// Fused flash attention — unchanged from R13 (2 CTAs/SM, ex2 softmax,
// single barrier per kv-chunk, Q pre-scaled by scale*log2e).
// =============================================================================
constexpr int QSTR = 136;
constexpr int KSTR = 136;
constexpr int Q_HLV = 128 * QSTR;
constexpr int KV_TILE = 64 * KSTR;
constexpr int KV_STAGE = 2 * KV_TILE;
constexpr int ATT_SMEM = (Q_HLV + 2 * KV_STAGE) * 2;   // 104448 B

__global__ __launch_bounds__(256, 2)
void fused_attn(const __half* __restrict__ Ta0, const __half* __restrict__ Tb0,
                __half* __restrict__ U0,
                const __half* __restrict__ Ta1, const __half* __restrict__ Tb1,
                __half* __restrict__ U1)
{
    extern __shared__ __half sm[];
    const uint32_t smb = smem_u32(sm);
    const int tid = threadIdx.x, wid = tid >> 5, lane = tid & 31;
    const int z = blockIdx.z;
    const __half* Ta = z ? Ta1 : Ta0;
    const __half* Tb = z ? Tb1 : Tb0;
    __half* U = z ? U1 : U0;

    const int bz = blockIdx.y, b = bz >> 3, h = bz & 7;
    const int n0 = blockIdx.x * 128;
    const int wrow = wid * 16;

    const size_t qbase = (size_t)(b * CN + n0) * C3D + CD + h * CHD;
    const size_t kbase = (size_t)b * CN * C3D + h * CHD;
    const size_t vbase = (size_t)b * CN * C3D + 2 * CD + h * CHD;

    auto load_q = [&]() {
        #pragma unroll
        for (int i = 0; i < 8; ++i) {
            const int idx = tid + i * 256;
            const int r = idx >> 4, c = (idx & 15) * 8;
            cp_async16(smb + (uint32_t)(r * QSTR + c) * 2,
                       Ta + qbase + (size_t)r * C3D + c);
        }
        cp_commit();
    };
    auto load_kv = [&](int mc, int buf) {
        const int m0 = mc * 64;
        const uint32_t base = smb + (uint32_t)(Q_HLV + buf * KV_STAGE) * 2;
        const __half* kp = Tb + kbase + (size_t)m0 * C3D;
        const __half* vp = Tb + vbase + (size_t)m0 * C3D;
        #pragma unroll
        for (int i = 0; i < 4; ++i) {
            const int idx = tid + i * 256;
            const int r = idx >> 4, c = (idx & 15) * 8;
            const uint32_t doff = (uint32_t)(r * KSTR + c) * 2;
            cp_async16(base + doff,               kp + (size_t)r * C3D + c);
            cp_async16(base + KV_TILE * 2 + doff, vp + (size_t)r * C3D + c);
        }
        cp_commit();
    };

    load_q();
    load_kv(0, 0);

    const int arow = lane & 15, acol = (lane >> 4) * 8;
    const uint32_t q_addr0 = smb + (uint32_t)((wrow + arow) * QSTR + acol) * 2;

    const int g = lane >> 2, tq = lane & 3;
    const int bq_row = (lane & 7) + ((lane >> 4) & 1) * 8;
    const int bq_col = ((lane >> 3) & 1) * 8;
    const int vq_row = lane & 15;
    const int vq_col = ((lane >> 4) & 1) * 8;

    float m0s = -1e30f, m1s = -1e30f, l0s = 0.f, l1s = 0.f;
    float o[16][4] = {};

    for (int mc = 0; mc < 8; ++mc) {
        const int buf = mc & 1;
        cp_wait<0>();
        __syncthreads();
        if (mc + 1 < 8) load_kv(mc + 1, buf ^ 1);

        const uint32_t base = smb + (uint32_t)(Q_HLV + buf * KV_STAGE) * 2;

        float s[8][4] = {};
        #pragma unroll
        for (int kf = 0; kf < 8; ++kf) {
            uint32_t qf[4];
            ldm_x4(qf, q_addr0 + (uint32_t)(kf * 16) * 2);
            #pragma unroll
            for (int p = 0; p < 4; ++p) {
                const uint32_t boff =
                    (uint32_t)((p * 16 + bq_row) * KSTR + kf * 16 + bq_col) * 2;
                uint32_t kk4[4];
                ldm_x4(kk4, base + boff);
                mma_f16(s[2 * p],     qf, &kk4[0]);
                mma_f16(s[2 * p + 1], qf, &kk4[2]);
            }
        }

        float mx0 = -1e30f, mx1 = -1e30f;
        #pragma unroll
        for (int nf = 0; nf < 8; ++nf) {
            mx0 = fmaxf(mx0, fmaxf(s[nf][0], s[nf][1]));
            mx1 = fmaxf(mx1, fmaxf(s[nf][2], s[nf][3]));
        }
        mx0 = fmaxf(mx0, __shfl_xor_sync(0xffffffffu, mx0, 1));
        mx0 = fmaxf(mx0, __shfl_xor_sync(0xffffffffu, mx0, 2));
        mx1 = fmaxf(mx1, __shfl_xor_sync(0xffffffffu, mx1, 1));
        mx1 = fmaxf(mx1, __shfl_xor_sync(0xffffffffu, mx1, 2));
        const float mn0 = fmaxf(m0s, mx0), mn1 = fmaxf(m1s, mx1);
        const float a0 = fexp2(m0s - mn0), a1 = fexp2(m1s - mn1);
        m0s = mn0; m1s = mn1;

        float rs0 = 0.f, rs1 = 0.f;
        __half2 pf[8][2];
        #pragma unroll
        for (int nf = 0; nf < 8; ++nf) {
            const float p0 = fexp2(s[nf][0] - mn0);
            const float p1 = fexp2(s[nf][1] - mn0);
            const float p2 = fexp2(s[nf][2] - mn1);
            const float p3 = fexp2(s[nf][3] - mn1);
            rs0 += p0 + p1; rs1 += p2 + p3;
            pf[nf][0] = __halves2half2(__float2half_rn(p0), __float2half_rn(p1));
            pf[nf][1] = __halves2half2(__float2half_rn(p2), __float2half_rn(p3));
        }
        rs0 += __shfl_xor_sync(0xffffffffu, rs0, 1);
        rs0 += __shfl_xor_sync(0xffffffffu, rs0, 2);
        rs1 += __shfl_xor_sync(0xffffffffu, rs1, 1);
        rs1 += __shfl_xor_sync(0xffffffffu, rs1, 2);
        l0s = l0s * a0 + rs0;
        l1s = l1s * a1 + rs1;

        #pragma unroll
        for (int nf2 = 0; nf2 < 16; ++nf2) {
            o[nf2][0] *= a0; o[nf2][1] *= a0;
            o[nf2][2] *= a1; o[nf2][3] *= a1;
        }

        #pragma unroll
        for (int kf2 = 0; kf2 < 4; ++kf2) {
            uint32_t pa[4];
            pa[0] = *reinterpret_cast<uint32_t*>(&pf[2 * kf2][0]);
            pa[1] = *reinterpret_cast<uint32_t*>(&pf[2 * kf2][1]);
            pa[2] = *reinterpret_cast<uint32_t*>(&pf[2 * kf2 + 1][0]);
            pa[3] = *reinterpret_cast<uint32_t*>(&pf[2 * kf2 + 1][1]);
            #pragma unroll
            for (int p = 0; p < 8; ++p) {
                const uint32_t boff =
                    (uint32_t)((kf2 * 16 + vq_row) * KSTR + p * 16 + vq_col) * 2;
                uint32_t vv4[4];
                ldm_x4_trans(vv4, base + KV_TILE * 2 + boff);
                mma_f16(o[2 * p],     pa, &vv4[0]);
                mma_f16(o[2 * p + 1], pa, &vv4[2]);
            }
        }
    }

    const float inv0 = 1.f / l0s, inv1 = 1.f / l1s;
    const int row0 = n0 + wrow + g;
    #pragma unroll
    for (int nf2 = 0; nf2 < 16; ++nf2) {
        const int col = h * CHD + nf2 * 8 + tq * 2;
        const size_t off0 = (size_t)(b * CN + row0) * CD + col;
        const size_t off1 = (size_t)(b * CN + row0 + 8) * CD + col;
        *reinterpret_cast<__half2*>(&U[off0]) =
            __halves2half2(__float2half_rn(o[nf2][0] * inv0), __float2half_rn(o[nf2][1] * inv0));
        *reinterpret_cast<__half2*>(&U[off1]) =
            __halves2half2(__float2half_rn(o[nf2][2] * inv1), __float2half_rn(o[nf2][3] * inv1));
    }
}

// =============================================================================
// fused prep: weight transposes (blocks [0, 10240)) + input fp16 conversion
// (blocks [10240, 12288): 1024 blocks x 2 modalities)
// =============================================================================
__global__ __launch_bounds__(256)
void prep_all(const float* __restrict__ Wv, const float* __restrict__ Wq,
              const float* __restrict__ Wvo, const float* __restrict__ Wqo,
              __half* __restrict__ Tv, __half* __restrict__ Tq,
              __half* __restrict__ Tvo, __half* __restrict__ Tqo,
              const float* __restrict__ xv, __half* __restrict__ hv,
              const float* __restrict__ xq, __half* __restrict__ hq,
              size_t nconv)
{
    const int bid = blockIdx.x;
    if (bid < 10240) {
        const float* W; __half* T; int K, N, local;
        if (bid < 3072)      { W = Wv;  T = Tv;  K = 1024; N = 3072; local = bid; }
        else if (bid < 6144) { W = Wq;  T = Tq;  K = 1024; N = 3072; local = bid - 3072; }
        else if (bid < 8192) { W = Wvo; T = Tvo; K = 2048; N = 1024; local = bid - 6144; }
        else                 { W = Wqo; T = Tqo; K = 2048; N = 1024; local = bid - 8192; }
        const int ntiles = N / 32;
        const int k0 = (local / ntiles) * 32, n0 = (local % ntiles) * 32;

        __shared__ float t[32][33];
        const int tx = threadIdx.x & 31, ty = threadIdx.x >> 5;
        for (int i = ty; i < 32; i += 8)
            t[i][tx] = W[(size_t)(k0 + i) * N + n0 + tx];
        __syncthreads();
        for (int i = ty; i < 32; i += 8)
            T[(size_t)(n0 + i) * K + k0 + tx] = __float2half_rn(t[tx][i]);
    } else {
        const int bid2 = bid - 10240;
        const int zz = bid2 >> 10;
        const int xb = bid2 & 1023;
        const float* x = zz ? xq : xv;
        __half* hh = zz ? hq : hv;
        const size_t stride = (size_t)1024 * 256 * 4;
        for (size_t i = ((size_t)xb * 256 + threadIdx.x) * 4; i < nconv; i += stride) {
            float4 v = *reinterpret_cast<const float4*>(x + i);
            *reinterpret_cast<__half2*>(hh + i) =
                __halves2half2(__float2half_rn(v.x), __float2half_rn(v.y));
            *reinterpret_cast<__half2*>(hh + i + 2) =
                __halves2half2(__float2half_rn(v.z), __float2half_rn(v.w));
        }
    }
}

// =============================================================================
// launch
// =============================================================================
extern "C" void kernel_launch(void* const* d_in, const int* in_sizes, int n_in,
                              void* d_out, int out_size)
{
    const float* v   = (const float*)d_in[0];
    const float* q   = (const float*)d_in[1];
    const float* Wv  = (const float*)d_in[2];
    const float* bv  = (const float*)d_in[3];
    const float* Wq  = (const float*)d_in[4];
    const float* bq  = (const float*)d_in[5];
    const float* Wvo = (const float*)d_in[6];
    const float* bvo = (const float*)d_in[7];
    const float* Wqo = (const float*)d_in[8];
    const float* bqo = (const float*)d_in[9];
    float* out = (float*)d_out;

    __half *vt, *qt, *vh, *qh, *vu, *qu, *Wvt, *Wqt, *Wvot, *Wqot;
    cudaGetSymbolAddress((void**)&vt, g_vt);   cudaGetSymbolAddress((void**)&qt, g_qt);
    cudaGetSymbolAddress((void**)&vh, g_vh);   cudaGetSymbolAddress((void**)&qh, g_qh);
    cudaGetSymbolAddress((void**)&vu, g_vu);   cudaGetSymbolAddress((void**)&qu, g_qu);
    cudaGetSymbolAddress((void**)&Wvt, g_Wvt); cudaGetSymbolAddress((void**)&Wqt, g_Wqt);
    cudaGetSymbolAddress((void**)&Wvot, g_Wvot); cudaGetSymbolAddress((void**)&Wqot, g_Wqot);

    cudaFuncSetAttribute(gemm_in,  cudaFuncAttributeMaxDynamicSharedMemorySize, GEMM_SMEM);
    cudaFuncSetAttribute(gemm_out, cudaFuncAttributeMaxDynamicSharedMemorySize, GEMM_SMEM);
    cudaFuncSetAttribute(fused_attn, cudaFuncAttributeMaxDynamicSharedMemorySize, ATT_SMEM);

    const dim3 t256(256), t512(512);
    const size_t nVD = (size_t)CM * CD;
    const size_t half = (size_t)CM * CD;

    // launch 0: fused prep (weight transposes + fp16 input copies)
    prep_all<<<12288, t256>>>(Wv, Wq, Wvo, Wqo, Wvt, Wqt, Wvot, Wqot,
                              v, vh, q, qh, nVD);

    // launch 1: input transforms (both modalities); query slice pre-scaled
    gemm_in<<<dim3(C3D / 128, CM / 256, 2), t512, GEMM_SMEM>>>(
        vh, qh, Wvt, Wqt, bv, bq, vt, qt, CM, C3D, CD);

    // launch 2: fused attention, both directions
    fused_attn<<<dim3(CN / 128, CB * CH, 2), t256, ATT_SMEM>>>(
        vt, qt, vu, qt, vt, qu);

    // launch 3: output transforms (virtual concat), both modalities
    gemm_out<<<dim3(CD / 128, CM / 256, 2), t512, GEMM_SMEM>>>(
        vh, vu, qh, qu, CD, Wvot, Wqot, bvo, bqo, out, half, CM, CD, 2 * CD);
}

// round 15
// speedup vs baseline: 1.0449x; 1.0449x over previous
#include <cuda_runtime.h>
#include <cuda_fp16.h>
#include <cstdint>
#include <math.h>

// Problem constants
constexpr int CB  = 32;
constexpr int CN  = 512;
constexpr int CD  = 1024;
constexpr int CH  = 8;
constexpr int CHD = 128;
constexpr int C3D = 3 * CD;
constexpr int CM  = CB * CN;   // 16384

// ---------------- scratch (device globals) ----------------------------------
__device__ __half g_vt[(size_t)CM * C3D];
__device__ __half g_qt[(size_t)CM * C3D];
__device__ __half g_vh[(size_t)CM * CD],  g_qh[(size_t)CM * CD];
__device__ __half g_vu[(size_t)CM * CD],  g_qu[(size_t)CM * CD];
__device__ __half g_Wvt[(size_t)C3D * CD],     g_Wqt[(size_t)C3D * CD];
__device__ __half g_Wvot[(size_t)CD * 2 * CD], g_Wqot[(size_t)CD * 2 * CD];

// ---------------- base-ISA PTX helpers ---------------------------------------
__device__ __forceinline__ uint32_t smem_u32(const void* p) {
    uint32_t a;
    asm("{ .reg .u64 t; cvta.to.shared.u64 t, %1; cvt.u32.u64 %0, t; }" : "=r"(a) : "l"(p));
    return a;
}
__device__ __forceinline__ void cp_async16(uint32_t dst, const void* src) {
    asm volatile("cp.async.cg.shared.global [%0], [%1], 16;" :: "r"(dst), "l"(src) : "memory");
}
__device__ __forceinline__ void cp_commit() { asm volatile("cp.async.commit_group;" ::: "memory"); }
template <int N>
__device__ __forceinline__ void cp_wait() { asm volatile("cp.async.wait_group %0;" :: "n"(N) : "memory"); }

__device__ __forceinline__ void ldm_x4(uint32_t* r, uint32_t addr) {
    asm volatile("ldmatrix.sync.aligned.m8n8.x4.shared.b16 {%0,%1,%2,%3}, [%4];"
        : "=r"(r[0]), "=r"(r[1]), "=r"(r[2]), "=r"(r[3]) : "r"(addr));
}
__device__ __forceinline__ void ldm_x4_trans(uint32_t* r, uint32_t addr) {
    asm volatile("ldmatrix.sync.aligned.m8n8.x4.trans.shared.b16 {%0,%1,%2,%3}, [%4];"
        : "=r"(r[0]), "=r"(r[1]), "=r"(r[2]), "=r"(r[3]) : "r"(addr));
}
__device__ __forceinline__ void mma_f16(float* c, const uint32_t* a, const uint32_t* b) {
    asm volatile("mma.sync.aligned.m16n8k16.row.col.f32.f16.f16.f32 "
        "{%0,%1,%2,%3}, {%4,%5,%6,%7}, {%8,%9}, {%0,%1,%2,%3};"
        : "+f"(c[0]), "+f"(c[1]), "+f"(c[2]), "+f"(c[3])
        : "r"(a[0]), "r"(a[1]), "r"(a[2]), "r"(a[3]), "r"(b[0]), "r"(b[1]));
}
__device__ __forceinline__ float fexp2(float x) {
    float y;
    asm("ex2.approx.ftz.f32 %0, %1;" : "=f"(y) : "f"(x));
    return y;
}

// Weight-GEMM tiling: CTA 128x128, BK=64, 8 warps 2Mx4N (warp 64x32),
// 256 threads, 3-stage pipeline, 2 CTAs/SM.  (R13-proven configuration)
constexpr int TSTR    = 72;
constexpr int TILE_H  = 128 * TSTR;
constexpr int STAGE_H = 2 * TILE_H;
constexpr int GEMM_SMEM = 3 * STAGE_H * 2;   // 110592 B
constexpr float Q_PREMULT = 0.08838834764831845f * 1.4426950408889634f;

// =============================================================================
// stage-1 GEMM (merged v/q): C = fp16(relu(A @ W + bias)); query slice
// (cols [CD, 2CD)) pre-multiplied by scale*log2(e).
// =============================================================================
__global__ __launch_bounds__(256, 2)
void gemm_in(const __half* __restrict__ A0g, const __half* __restrict__ A1g,
             const __half* __restrict__ B0g, const __half* __restrict__ B1g,
             const float* __restrict__ bias0, const float* __restrict__ bias1,
             __half* __restrict__ C0g, __half* __restrict__ C1g,
             int M, int N, int K)
{
    extern __shared__ __half sm[];
    const uint32_t smb = smem_u32(sm);
    const int tid = threadIdx.x, wid = tid >> 5, lane = tid & 31;
    const int z = blockIdx.z;
    const __half* Ag = z ? A1g : A0g;
    const __half* Bg = z ? B1g : B0g;
    const float* bias = z ? bias1 : bias0;
    __half* Cg = z ? C1g : C0g;

    const int bm0 = blockIdx.y * 128, bn0 = blockIdx.x * 128;
    const int nk = K / 64;
    const int mw = (wid & 1) * 64, nw = (wid >> 1) * 32;

    auto load_stage = [&](int kc, int buf) {
        const int kk = kc * 64;
        const __half* a = Ag + (size_t)bm0 * K + kk;
        const __half* b = Bg + (size_t)bn0 * K + kk;
        const uint32_t base = smb + (uint32_t)buf * STAGE_H * 2;
        #pragma unroll
        for (int i = 0; i < 4; ++i) {
            const int idx = tid + i * 256;
            const int r = idx >> 3, c = (idx & 7) * 8;
            const uint32_t doff = (uint32_t)(r * TSTR + c) * 2;
            cp_async16(base + doff,              a + (size_t)r * K + c);
            cp_async16(base + TILE_H * 2 + doff, b + (size_t)r * K + c);
        }
        cp_commit();
    };

    float acc[4][4][4] = {};
    const int arow = lane & 15, acol = (lane >> 4) * 8;
    const int bq_row = (lane & 7) + ((lane >> 4) & 1) * 8;
    const int bq_col = ((lane >> 3) & 1) * 8;

    load_stage(0, 0);
    load_stage(1, 1);
    for (int kc = 0; kc < nk; ++kc) {
        const int buf = kc % 3;
        if (kc + 1 < nk) cp_wait<1>(); else cp_wait<0>();
        __syncthreads();
        if (kc + 2 < nk) load_stage(kc + 2, (kc + 2) % 3);
        const uint32_t base = smb + (uint32_t)buf * STAGE_H * 2;
        #pragma unroll
        for (int ks = 0; ks < 4; ++ks) {
            const int k0 = ks * 16;
            uint32_t bb[2][4];
            #pragma unroll
            for (int p = 0; p < 2; ++p) {
                const uint32_t boff =
                    (uint32_t)((nw + p * 16 + bq_row) * TSTR + k0 + bq_col) * 2;
                ldm_x4(bb[p], base + TILE_H * 2 + boff);
            }
            #pragma unroll
            for (int mi = 0; mi < 4; ++mi) {
                uint32_t ah[4];
                const uint32_t aoff = (uint32_t)((mw + mi * 16 + arow) * TSTR + k0 + acol) * 2;
                ldm_x4(ah, base + aoff);
                #pragma unroll
                for (int p = 0; p < 2; ++p) {
                    mma_f16(acc[mi][2 * p],     ah, &bb[p][0]);
                    mma_f16(acc[mi][2 * p + 1], ah, &bb[p][2]);
                }
            }
        }
    }

    const int g = lane >> 2, tq = lane & 3;
    #pragma unroll
    for (int mi = 0; mi < 4; ++mi) {
        const int row0 = bm0 + mw + mi * 16 + g;
        #pragma unroll
        for (int ni = 0; ni < 4; ++ni) {
            const int col = bn0 + nw + ni * 8 + tq * 2;
            const float mult = (col >= CD && col < 2 * CD) ? Q_PREMULT : 1.0f;
            const float b0 = __ldg(&bias[col]), b1 = __ldg(&bias[col + 1]);
            *reinterpret_cast<__half2*>(&Cg[(size_t)row0 * N + col]) = __halves2half2(
                __float2half_rn(fmaxf(acc[mi][ni][0] + b0, 0.f) * mult),
                __float2half_rn(fmaxf(acc[mi][ni][1] + b1, 0.f) * mult));
            *reinterpret_cast<__half2*>(&Cg[(size_t)(row0 + 8) * N + col]) = __halves2half2(
                __float2half_rn(fmaxf(acc[mi][ni][2] + b0, 0.f) * mult),
                __float2half_rn(fmaxf(acc[mi][ni][3] + b1, 0.f) * mult));
        }
    }
}

// =============================================================================
// stage-5 GEMM (merged v/q): C = relu(concat(A0,A1) @ W + bias), fp32 out.
// Output is write-once (never re-read on device) -> streaming stores (__stcs).
// =============================================================================
__global__ __launch_bounds__(256, 2)
void gemm_out(const __half* __restrict__ A0v, const __half* __restrict__ A1v,
              const __half* __restrict__ A0q, const __half* __restrict__ A1q,
              int K0,
              const __half* __restrict__ Bv, const __half* __restrict__ Bq,
              const float* __restrict__ biasv, const float* __restrict__ biasq,
              float* __restrict__ C, size_t zoff,
              int M, int N, int K)
{
    extern __shared__ __half sm[];
    const uint32_t smb = smem_u32(sm);
    const int tid = threadIdx.x, wid = tid >> 5, lane = tid & 31;
    const int z = blockIdx.z;
    const __half* A0g = z ? A0q : A0v;
    const __half* A1g = z ? A1q : A1v;
    const __half* Bg  = z ? Bq  : Bv;
    const float* bias = z ? biasq : biasv;
    float* Cg = C + (size_t)z * zoff;

    const int bm0 = blockIdx.y * 128, bn0 = blockIdx.x * 128;
    const int nk = K / 64, K1 = K - K0;
    const int mw = (wid & 1) * 64, nw = (wid >> 1) * 32;

    auto load_stage = [&](int kc, int buf) {
        const int kk = kc * 64;
        const __half* a; int ldA, ka;
        if (kk < K0) { a = A0g; ldA = K0; ka = kk; }
        else         { a = A1g; ldA = K1; ka = kk - K0; }
        a += (size_t)bm0 * ldA + ka;
        const __half* b = Bg + (size_t)bn0 * K + kk;
        const uint32_t base = smb + (uint32_t)buf * STAGE_H * 2;
        #pragma unroll
        for (int i = 0; i < 4; ++i) {
            const int idx = tid + i * 256;
            const int r = idx >> 3, c = (idx & 7) * 8;
            const uint32_t doff = (uint32_t)(r * TSTR + c) * 2;
            cp_async16(base + doff,              a + (size_t)r * ldA + c);
            cp_async16(base + TILE_H * 2 + doff, b + (size_t)r * K + c);
        }
        cp_commit();
    };

    float acc[4][4][4] = {};
    const int arow = lane & 15, acol = (lane >> 4) * 8;
    const int bq_row = (lane & 7) + ((lane >> 4) & 1) * 8;
    const int bq_col = ((lane >> 3) & 1) * 8;

    load_stage(0, 0);
    load_stage(1, 1);
    for (int kc = 0; kc < nk; ++kc) {
        const int buf = kc % 3;
        if (kc + 1 < nk) cp_wait<1>(); else cp_wait<0>();
        __syncthreads();
        if (kc + 2 < nk) load_stage(kc + 2, (kc + 2) % 3);
        const uint32_t base = smb + (uint32_t)buf * STAGE_H * 2;
        #pragma unroll
        for (int ks = 0; ks < 4; ++ks) {
            const int k0 = ks * 16;
            uint32_t bb[2][4];
            #pragma unroll
            for (int p = 0; p < 2; ++p) {
                const uint32_t boff =
                    (uint32_t)((nw + p * 16 + bq_row) * TSTR + k0 + bq_col) * 2;
                ldm_x4(bb[p], base + TILE_H * 2 + boff);
            }
            #pragma unroll
            for (int mi = 0; mi < 4; ++mi) {
                uint32_t ah[4];
                const uint32_t aoff = (uint32_t)((mw + mi * 16 + arow) * TSTR + k0 + acol) * 2;
                ldm_x4(ah, base + aoff);
                #pragma unroll
                for (int p = 0; p < 2; ++p) {
                    mma_f16(acc[mi][2 * p],     ah, &bb[p][0]);
                    mma_f16(acc[mi][2 * p + 1], ah, &bb[p][2]);
                }
            }
        }
    }

    const int g = lane >> 2, tq = lane & 3;
    #pragma unroll
    for (int mi = 0; mi < 4; ++mi) {
        const int row0 = bm0 + mw + mi * 16 + g;
        #pragma unroll
        for (int ni = 0; ni < 4; ++ni) {
            const int col = bn0 + nw + ni * 8 + tq * 2;
            const float b0 = __ldg(&bias[col]), b1 = __ldg(&bias[col + 1]);
            float2 o0, o1;
            o0.x = fmaxf(acc[mi][ni][0] + b0, 0.f);
            o0.y = fmaxf(acc[mi][ni][1] + b1, 0.f);
            o1.x = fmaxf(acc[mi][ni][2] + b0, 0.f);
            o1.y = fmaxf(acc[mi][ni][3] + b1, 0.f);
            __stcs(reinterpret_cast<float2*>(&Cg[(size_t)row0 * N + col]), o0);
            __stcs(reinterpret_cast<float2*>(&Cg[(size_t)(row0 + 8) * N + col]), o1);
        }
    }
}

// =============================================================================
// Fused flash attention — 2 CTAs/SM; ex2 softmax; single barrier per kv-chunk;
// Q pre-scaled by scale*log2e in gemm_in.
// =============================================================================
constexpr int QSTR = 136;
constexpr int KSTR = 136;
constexpr int Q_HLV = 128 * QSTR;
constexpr int KV_TILE = 64 * KSTR;
constexpr int KV_STAGE = 2 * KV_TILE;
constexpr int ATT_SMEM = (Q_HLV + 2 * KV_STAGE) * 2;   // 104448 B

__global__ __launch_bounds__(256, 2)
void fused_attn(const __half* __restrict__ Ta0, const __half* __restrict__ Tb0,
                __half* __restrict__ U0,
                const __half* __restrict__ Ta1, const __half* __restrict__ Tb1,
                __half* __restrict__ U1)
{
    extern __shared__ __half sm[];
    const uint32_t smb = smem_u32(sm);
    const int tid = threadIdx.x, wid = tid >> 5, lane = tid & 31;
    const int z = blockIdx.z;
    const __half* Ta = z ? Ta1 : Ta0;
    const __half* Tb = z ? Tb1 : Tb0;
    __half* U = z ? U1 : U0;

    const int bz = blockIdx.y, b = bz >> 3, h = bz & 7;
    const int n0 = blockIdx.x * 128;
    const int wrow = wid * 16;

    const size_t qbase = (size_t)(b * CN + n0) * C3D + CD + h * CHD;
    const size_t kbase = (size_t)b * CN * C3D + h * CHD;
    const size_t vbase = (size_t)b * CN * C3D + 2 * CD + h * CHD;

    auto load_q = [&]() {
        #pragma unroll
        for (int i = 0; i < 8; ++i) {
            const int idx = tid + i * 256;
            const int r = idx >> 4, c = (idx & 15) * 8;
            cp_async16(smb + (uint32_t)(r * QSTR + c) * 2,
                       Ta + qbase + (size_t)r * C3D + c);
        }
        cp_commit();
    };
    auto load_kv = [&](int mc, int buf) {
        const int m0 = mc * 64;
        const uint32_t base = smb + (uint32_t)(Q_HLV + buf * KV_STAGE) * 2;
        const __half* kp = Tb + kbase + (size_t)m0 * C3D;
        const __half* vp = Tb + vbase + (size_t)m0 * C3D;
        #pragma unroll
        for (int i = 0; i < 4; ++i) {
            const int idx = tid + i * 256;
            const int r = idx >> 4, c = (idx & 15) * 8;
            const uint32_t doff = (uint32_t)(r * KSTR + c) * 2;
            cp_async16(base + doff,               kp + (size_t)r * C3D + c);
            cp_async16(base + KV_TILE * 2 + doff, vp + (size_t)r * C3D + c);
        }
        cp_commit();
    };

    load_q();
    load_kv(0, 0);

    const int arow = lane & 15, acol = (lane >> 4) * 8;
    const uint32_t q_addr0 = smb + (uint32_t)((wrow + arow) * QSTR + acol) * 2;

    const int g = lane >> 2, tq = lane & 3;
    const int bq_row = (lane & 7) + ((lane >> 4) & 1) * 8;
    const int bq_col = ((lane >> 3) & 1) * 8;
    const int vq_row = lane & 15;
    const int vq_col = ((lane >> 4) & 1) * 8;

    float m0s = -1e30f, m1s = -1e30f, l0s = 0.f, l1s = 0.f;
    float o[16][4] = {};

    for (int mc = 0; mc < 8; ++mc) {
        const int buf = mc & 1;
        cp_wait<0>();
        __syncthreads();
        if (mc + 1 < 8) load_kv(mc + 1, buf ^ 1);

        const uint32_t base = smb + (uint32_t)(Q_HLV + buf * KV_STAGE) * 2;

        float s[8][4] = {};
        #pragma unroll
        for (int kf = 0; kf < 8; ++kf) {
            uint32_t qf[4];
            ldm_x4(qf, q_addr0 + (uint32_t)(kf * 16) * 2);
            #pragma unroll
            for (int p = 0; p < 4; ++p) {
                const uint32_t boff =
                    (uint32_t)((p * 16 + bq_row) * KSTR + kf * 16 + bq_col) * 2;
                uint32_t kk4[4];
                ldm_x4(kk4, base + boff);
                mma_f16(s[2 * p],     qf, &kk4[0]);
                mma_f16(s[2 * p + 1], qf, &kk4[2]);
            }
        }

        float mx0 = -1e30f, mx1 = -1e30f;
        #pragma unroll
        for (int nf = 0; nf < 8; ++nf) {
            mx0 = fmaxf(mx0, fmaxf(s[nf][0], s[nf][1]));
            mx1 = fmaxf(mx1, fmaxf(s[nf][2], s[nf][3]));
        }
        mx0 = fmaxf(mx0, __shfl_xor_sync(0xffffffffu, mx0, 1));
        mx0 = fmaxf(mx0, __shfl_xor_sync(0xffffffffu, mx0, 2));
        mx1 = fmaxf(mx1, __shfl_xor_sync(0xffffffffu, mx1, 1));
        mx1 = fmaxf(mx1, __shfl_xor_sync(0xffffffffu, mx1, 2));
        const float mn0 = fmaxf(m0s, mx0), mn1 = fmaxf(m1s, mx1);
        const float a0 = fexp2(m0s - mn0), a1 = fexp2(m1s - mn1);
        m0s = mn0; m1s = mn1;

        float rs0 = 0.f, rs1 = 0.f;
        __half2 pf[8][2];
        #pragma unroll
        for (int nf = 0; nf < 8; ++nf) {
            const float p0 = fexp2(s[nf][0] - mn0);
            const float p1 = fexp2(s[nf][1] - mn0);
            const float p2 = fexp2(s[nf][2] - mn1);
            const float p3 = fexp2(s[nf][3] - mn1);
            rs0 += p0 + p1; rs1 += p2 + p3;
            pf[nf][0] = __halves2half2(__float2half_rn(p0), __float2half_rn(p1));
            pf[nf][1] = __halves2half2(__float2half_rn(p2), __float2half_rn(p3));
        }
        rs0 += __shfl_xor_sync(0xffffffffu, rs0, 1);
        rs0 += __shfl_xor_sync(0xffffffffu, rs0, 2);
        rs1 += __shfl_xor_sync(0xffffffffu, rs1, 1);
        rs1 += __shfl_xor_sync(0xffffffffu, rs1, 2);
        l0s = l0s * a0 + rs0;
        l1s = l1s * a1 + rs1;

        #pragma unroll
        for (int nf2 = 0; nf2 < 16; ++nf2) {
            o[nf2][0] *= a0; o[nf2][1] *= a0;
            o[nf2][2] *= a1; o[nf2][3] *= a1;
        }

        #pragma unroll
        for (int kf2 = 0; kf2 < 4; ++kf2) {
            uint32_t pa[4];
            pa[0] = *reinterpret_cast<uint32_t*>(&pf[2 * kf2][0]);
            pa[1] = *reinterpret_cast<uint32_t*>(&pf[2 * kf2][1]);
            pa[2] = *reinterpret_cast<uint32_t*>(&pf[2 * kf2 + 1][0]);
            pa[3] = *reinterpret_cast<uint32_t*>(&pf[2 * kf2 + 1][1]);
            #pragma unroll
            for (int p = 0; p < 8; ++p) {
                const uint32_t boff =
                    (uint32_t)((kf2 * 16 + vq_row) * KSTR + p * 16 + vq_col) * 2;
                uint32_t vv4[4];
                ldm_x4_trans(vv4, base + KV_TILE * 2 + boff);
                mma_f16(o[2 * p],     pa, &vv4[0]);
                mma_f16(o[2 * p + 1], pa, &vv4[2]);
            }
        }
    }

    const float inv0 = 1.f / l0s, inv1 = 1.f / l1s;
    const int row0 = n0 + wrow + g;
    #pragma unroll
    for (int nf2 = 0; nf2 < 16; ++nf2) {
        const int col = h * CHD + nf2 * 8 + tq * 2;
        const size_t off0 = (size_t)(b * CN + row0) * CD + col;
        const size_t off1 = (size_t)(b * CN + row0 + 8) * CD + col;
        *reinterpret_cast<__half2*>(&U[off0]) =
            __halves2half2(__float2half_rn(o[nf2][0] * inv0), __float2half_rn(o[nf2][1] * inv0));
        *reinterpret_cast<__half2*>(&U[off1]) =
            __halves2half2(__float2half_rn(o[nf2][2] * inv1), __float2half_rn(o[nf2][3] * inv1));
    }
}

// =============================================================================
// precompute kernels (R13 configuration)
// =============================================================================
__global__ __launch_bounds__(256)
void to_half2(const float* __restrict__ x0, __half* __restrict__ h0,
              const float* __restrict__ x1, __half* __restrict__ h1, size_t n)
{
    const float* x = blockIdx.z ? x1 : x0;
    __half* hh = blockIdx.z ? h1 : h0;
    const size_t stride = (size_t)gridDim.x * blockDim.x * 4;
    for (size_t i = ((size_t)blockIdx.x * blockDim.x + threadIdx.x) * 4; i < n; i += stride) {
        float4 v = *reinterpret_cast<const float4*>(x + i);
        *reinterpret_cast<__half2*>(hh + i) =
            __halves2half2(__float2half_rn(v.x), __float2half_rn(v.y));
        *reinterpret_cast<__half2*>(hh + i + 2) =
            __halves2half2(__float2half_rn(v.z), __float2half_rn(v.w));
    }
}

__global__ __launch_bounds__(256)
void transpose_all(const float* __restrict__ Wv, const float* __restrict__ Wq,
                   const float* __restrict__ Wvo, const float* __restrict__ Wqo,
                   __half* __restrict__ Tv, __half* __restrict__ Tq,
                   __half* __restrict__ Tvo, __half* __restrict__ Tqo)
{
    const int bid = blockIdx.x;
    const float* W; __half* T; int K, N, local;
    if (bid < 3072)      { W = Wv;  T = Tv;  K = 1024; N = 3072; local = bid; }
    else if (bid < 6144) { W = Wq;  T = Tq;  K = 1024; N = 3072; local = bid - 3072; }
    else if (bid < 8192) { W = Wvo; T = Tvo; K = 2048; N = 1024; local = bid - 6144; }
    else                 { W = Wqo; T = Tqo; K = 2048; N = 1024; local = bid - 8192; }
    const int ntiles = N / 32;
    const int k0 = (local / ntiles) * 32, n0 = (local % ntiles) * 32;

    __shared__ float t[32][33];
    const int tx = threadIdx.x & 31, ty = threadIdx.x >> 5;
    for (int i = ty; i < 32; i += 8)
        t[i][tx] = W[(size_t)(k0 + i) * N + n0 + tx];
    __syncthreads();
    for (int i = ty; i < 32; i += 8)
        T[(size_t)(n0 + i) * K + k0 + tx] = __float2half_rn(t[tx][i]);
}

// =============================================================================
// launch
// =============================================================================
extern "C" void kernel_launch(void* const* d_in, const int* in_sizes, int n_in,
                              void* d_out, int out_size)
{
    const float* v   = (const float*)d_in[0];
    const float* q   = (const float*)d_in[1];
    const float* Wv  = (const float*)d_in[2];
    const float* bv  = (const float*)d_in[3];
    const float* Wq  = (const float*)d_in[4];
    const float* bq  = (const float*)d_in[5];
    const float* Wvo = (const float*)d_in[6];
    const float* bvo = (const float*)d_in[7];
    const float* Wqo = (const float*)d_in[8];
    const float* bqo = (const float*)d_in[9];
    float* out = (float*)d_out;

    __half *vt, *qt, *vh, *qh, *vu, *qu, *Wvt, *Wqt, *Wvot, *Wqot;
    cudaGetSymbolAddress((void**)&vt, g_vt);   cudaGetSymbolAddress((void**)&qt, g_qt);
    cudaGetSymbolAddress((void**)&vh, g_vh);   cudaGetSymbolAddress((void**)&qh, g_qh);
    cudaGetSymbolAddress((void**)&vu, g_vu);   cudaGetSymbolAddress((void**)&qu, g_qu);
    cudaGetSymbolAddress((void**)&Wvt, g_Wvt); cudaGetSymbolAddress((void**)&Wqt, g_Wqt);
    cudaGetSymbolAddress((void**)&Wvot, g_Wvot); cudaGetSymbolAddress((void**)&Wqot, g_Wqot);

    cudaFuncSetAttribute(gemm_in,  cudaFuncAttributeMaxDynamicSharedMemorySize, GEMM_SMEM);
    cudaFuncSetAttribute(gemm_out, cudaFuncAttributeMaxDynamicSharedMemorySize, GEMM_SMEM);
    cudaFuncSetAttribute(fused_attn, cudaFuncAttributeMaxDynamicSharedMemorySize, ATT_SMEM);

    const dim3 t256(256);
    const size_t nVD = (size_t)CM * CD;
    const size_t half = (size_t)CM * CD;

    // prep
    to_half2<<<dim3(1024, 1, 2), t256>>>(v, vh, q, qh, nVD);
    transpose_all<<<10240, t256>>>(Wv, Wq, Wvo, Wqo, Wvt, Wqt, Wvot, Wqot);

    // input transforms (both modalities); query slice pre-scaled
    gemm_in<<<dim3(C3D / 128, CM / 128, 2), t256, GEMM_SMEM>>>(
        vh, qh, Wvt, Wqt, bv, bq, vt, qt, CM, C3D, CD);

    // fused attention, both directions
    fused_attn<<<dim3(CN / 128, CB * CH, 2), t256, ATT_SMEM>>>(
        vt, qt, vu, qt, vt, qu);

    // output transforms (virtual concat), both modalities
    gemm_out<<<dim3(CD / 128, CM / 128, 2), t256, GEMM_SMEM>>>(
        vh, vu, qh, qu, CD, Wvot, Wqot, bvo, bqo, out, half, CM, CD, 2 * CD);
}

// round 16
// speedup vs baseline: 1.0544x; 1.0091x over previous
#include <cuda_runtime.h>
#include <cuda_fp16.h>
#include <cstdint>
#include <math.h>

// Problem constants
constexpr int CB  = 32;
constexpr int CN  = 512;
constexpr int CD  = 1024;
constexpr int CH  = 8;
constexpr int CHD = 128;
constexpr int C3D = 3 * CD;
constexpr int CM  = CB * CN;   // 16384

// ---------------- scratch (device globals) ----------------------------------
__device__ __half g_vt[(size_t)CM * C3D];
__device__ __half g_qt[(size_t)CM * C3D];
__device__ __half g_vh[(size_t)CM * CD],  g_qh[(size_t)CM * CD];
__device__ __half g_vu[(size_t)CM * CD],  g_qu[(size_t)CM * CD];
__device__ __half g_Wvt[(size_t)C3D * CD],     g_Wqt[(size_t)C3D * CD];
__device__ __half g_Wvot[(size_t)CD * 2 * CD], g_Wqot[(size_t)CD * 2 * CD];

// ---------------- base-ISA PTX helpers ---------------------------------------
__device__ __forceinline__ uint32_t smem_u32(const void* p) {
    uint32_t a;
    asm("{ .reg .u64 t; cvta.to.shared.u64 t, %1; cvt.u32.u64 %0, t; }" : "=r"(a) : "l"(p));
    return a;
}
__device__ __forceinline__ void cp_async16(uint32_t dst, const void* src) {
    asm volatile("cp.async.cg.shared.global [%0], [%1], 16;" :: "r"(dst), "l"(src) : "memory");
}
__device__ __forceinline__ void cp_commit() { asm volatile("cp.async.commit_group;" ::: "memory"); }
template <int N>
__device__ __forceinline__ void cp_wait() { asm volatile("cp.async.wait_group %0;" :: "n"(N) : "memory"); }

__device__ __forceinline__ void ldm_x4(uint32_t* r, uint32_t addr) {
    asm volatile("ldmatrix.sync.aligned.m8n8.x4.shared.b16 {%0,%1,%2,%3}, [%4];"
        : "=r"(r[0]), "=r"(r[1]), "=r"(r[2]), "=r"(r[3]) : "r"(addr));
}
__device__ __forceinline__ void ldm_x4_trans(uint32_t* r, uint32_t addr) {
    asm volatile("ldmatrix.sync.aligned.m8n8.x4.trans.shared.b16 {%0,%1,%2,%3}, [%4];"
        : "=r"(r[0]), "=r"(r[1]), "=r"(r[2]), "=r"(r[3]) : "r"(addr));
}
__device__ __forceinline__ void mma_f16(float* c, const uint32_t* a, const uint32_t* b) {
    asm volatile("mma.sync.aligned.m16n8k16.row.col.f32.f16.f16.f32 "
        "{%0,%1,%2,%3}, {%4,%5,%6,%7}, {%8,%9}, {%0,%1,%2,%3};"
        : "+f"(c[0]), "+f"(c[1]), "+f"(c[2]), "+f"(c[3])
        : "r"(a[0]), "r"(a[1]), "r"(a[2]), "r"(a[3]), "r"(b[0]), "r"(b[1]));
}
__device__ __forceinline__ float fexp2(float x) {
    float y;
    asm("ex2.approx.ftz.f32 %0, %1;" : "=f"(y) : "f"(x));
    return y;
}

// Weight-GEMM tiling: CTA 128x128, BK=64, 8 warps 2Mx4N (warp 64x32),
// 256 threads, 3-stage pipeline, 2 CTAs/SM.  (R13/R15-proven configuration)
constexpr int TSTR    = 72;
constexpr int TILE_H  = 128 * TSTR;
constexpr int STAGE_H = 2 * TILE_H;
constexpr int GEMM_SMEM = 3 * STAGE_H * 2;   // 110592 B
constexpr float Q_PREMULT = 0.08838834764831845f * 1.4426950408889634f;

// =============================================================================
// stage-1 GEMM (merged v/q): C = fp16(relu(A @ W + bias)); query slice
// (cols [CD, 2CD)) pre-multiplied by scale*log2(e).
// =============================================================================
__global__ __launch_bounds__(256, 2)
void gemm_in(const __half* __restrict__ A0g, const __half* __restrict__ A1g,
             const __half* __restrict__ B0g, const __half* __restrict__ B1g,
             const float* __restrict__ bias0, const float* __restrict__ bias1,
             __half* __restrict__ C0g, __half* __restrict__ C1g,
             int M, int N, int K)
{
    extern __shared__ __half sm[];
    const uint32_t smb = smem_u32(sm);
    const int tid = threadIdx.x, wid = tid >> 5, lane = tid & 31;
    const int z = blockIdx.z;
    const __half* Ag = z ? A1g : A0g;
    const __half* Bg = z ? B1g : B0g;
    const float* bias = z ? bias1 : bias0;
    __half* Cg = z ? C1g : C0g;

    const int bm0 = blockIdx.y * 128, bn0 = blockIdx.x * 128;
    const int nk = K / 64;
    const int mw = (wid & 1) * 64, nw = (wid >> 1) * 32;

    auto load_stage = [&](int kc, int buf) {
        const int kk = kc * 64;
        const __half* a = Ag + (size_t)bm0 * K + kk;
        const __half* b = Bg + (size_t)bn0 * K + kk;
        const uint32_t base = smb + (uint32_t)buf * STAGE_H * 2;
        #pragma unroll
        for (int i = 0; i < 4; ++i) {
            const int idx = tid + i * 256;
            const int r = idx >> 3, c = (idx & 7) * 8;
            const uint32_t doff = (uint32_t)(r * TSTR + c) * 2;
            cp_async16(base + doff,              a + (size_t)r * K + c);
            cp_async16(base + TILE_H * 2 + doff, b + (size_t)r * K + c);
        }
        cp_commit();
    };

    float acc[4][4][4] = {};
    const int arow = lane & 15, acol = (lane >> 4) * 8;
    const int bq_row = (lane & 7) + ((lane >> 4) & 1) * 8;
    const int bq_col = ((lane >> 3) & 1) * 8;

    load_stage(0, 0);
    load_stage(1, 1);
    for (int kc = 0; kc < nk; ++kc) {
        const int buf = kc % 3;
        if (kc + 1 < nk) cp_wait<1>(); else cp_wait<0>();
        __syncthreads();
        if (kc + 2 < nk) load_stage(kc + 2, (kc + 2) % 3);
        const uint32_t base = smb + (uint32_t)buf * STAGE_H * 2;
        #pragma unroll
        for (int ks = 0; ks < 4; ++ks) {
            const int k0 = ks * 16;
            uint32_t bb[2][4];
            #pragma unroll
            for (int p = 0; p < 2; ++p) {
                const uint32_t boff =
                    (uint32_t)((nw + p * 16 + bq_row) * TSTR + k0 + bq_col) * 2;
                ldm_x4(bb[p], base + TILE_H * 2 + boff);
            }
            #pragma unroll
            for (int mi = 0; mi < 4; ++mi) {
                uint32_t ah[4];
                const uint32_t aoff = (uint32_t)((mw + mi * 16 + arow) * TSTR + k0 + acol) * 2;
                ldm_x4(ah, base + aoff);
                #pragma unroll
                for (int p = 0; p < 2; ++p) {
                    mma_f16(acc[mi][2 * p],     ah, &bb[p][0]);
                    mma_f16(acc[mi][2 * p + 1], ah, &bb[p][2]);
                }
            }
        }
    }

    const int g = lane >> 2, tq = lane & 3;
    #pragma unroll
    for (int mi = 0; mi < 4; ++mi) {
        const int row0 = bm0 + mw + mi * 16 + g;
        #pragma unroll
        for (int ni = 0; ni < 4; ++ni) {
            const int col = bn0 + nw + ni * 8 + tq * 2;
            const float mult = (col >= CD && col < 2 * CD) ? Q_PREMULT : 1.0f;
            const float b0 = __ldg(&bias[col]), b1 = __ldg(&bias[col + 1]);
            *reinterpret_cast<__half2*>(&Cg[(size_t)row0 * N + col]) = __halves2half2(
                __float2half_rn(fmaxf(acc[mi][ni][0] + b0, 0.f) * mult),
                __float2half_rn(fmaxf(acc[mi][ni][1] + b1, 0.f) * mult));
            *reinterpret_cast<__half2*>(&Cg[(size_t)(row0 + 8) * N + col]) = __halves2half2(
                __float2half_rn(fmaxf(acc[mi][ni][2] + b0, 0.f) * mult),
                __float2half_rn(fmaxf(acc[mi][ni][3] + b1, 0.f) * mult));
        }
    }
}

// =============================================================================
// stage-5 GEMM (merged v/q): C = relu(concat(A0,A1) @ W + bias), fp32 out.
// Output is write-once -> streaming stores (__stcs).
// =============================================================================
__global__ __launch_bounds__(256, 2)
void gemm_out(const __half* __restrict__ A0v, const __half* __restrict__ A1v,
              const __half* __restrict__ A0q, const __half* __restrict__ A1q,
              int K0,
              const __half* __restrict__ Bv, const __half* __restrict__ Bq,
              const float* __restrict__ biasv, const float* __restrict__ biasq,
              float* __restrict__ C, size_t zoff,
              int M, int N, int K)
{
    extern __shared__ __half sm[];
    const uint32_t smb = smem_u32(sm);
    const int tid = threadIdx.x, wid = tid >> 5, lane = tid & 31;
    const int z = blockIdx.z;
    const __half* A0g = z ? A0q : A0v;
    const __half* A1g = z ? A1q : A1v;
    const __half* Bg  = z ? Bq  : Bv;
    const float* bias = z ? biasq : biasv;
    float* Cg = C + (size_t)z * zoff;

    const int bm0 = blockIdx.y * 128, bn0 = blockIdx.x * 128;
    const int nk = K / 64, K1 = K - K0;
    const int mw = (wid & 1) * 64, nw = (wid >> 1) * 32;

    auto load_stage = [&](int kc, int buf) {
        const int kk = kc * 64;
        const __half* a; int ldA, ka;
        if (kk < K0) { a = A0g; ldA = K0; ka = kk; }
        else         { a = A1g; ldA = K1; ka = kk - K0; }
        a += (size_t)bm0 * ldA + ka;
        const __half* b = Bg + (size_t)bn0 * K + kk;
        const uint32_t base = smb + (uint32_t)buf * STAGE_H * 2;
        #pragma unroll
        for (int i = 0; i < 4; ++i) {
            const int idx = tid + i * 256;
            const int r = idx >> 3, c = (idx & 7) * 8;
            const uint32_t doff = (uint32_t)(r * TSTR + c) * 2;
            cp_async16(base + doff,              a + (size_t)r * ldA + c);
            cp_async16(base + TILE_H * 2 + doff, b + (size_t)r * K + c);
        }
        cp_commit();
    };

    float acc[4][4][4] = {};
    const int arow = lane & 15, acol = (lane >> 4) * 8;
    const int bq_row = (lane & 7) + ((lane >> 4) & 1) * 8;
    const int bq_col = ((lane >> 3) & 1) * 8;

    load_stage(0, 0);
    load_stage(1, 1);
    for (int kc = 0; kc < nk; ++kc) {
        const int buf = kc % 3;
        if (kc + 1 < nk) cp_wait<1>(); else cp_wait<0>();
        __syncthreads();
        if (kc + 2 < nk) load_stage(kc + 2, (kc + 2) % 3);
        const uint32_t base = smb + (uint32_t)buf * STAGE_H * 2;
        #pragma unroll
        for (int ks = 0; ks < 4; ++ks) {
            const int k0 = ks * 16;
            uint32_t bb[2][4];
            #pragma unroll
            for (int p = 0; p < 2; ++p) {
                const uint32_t boff =
                    (uint32_t)((nw + p * 16 + bq_row) * TSTR + k0 + bq_col) * 2;
                ldm_x4(bb[p], base + TILE_H * 2 + boff);
            }
            #pragma unroll
            for (int mi = 0; mi < 4; ++mi) {
                uint32_t ah[4];
                const uint32_t aoff = (uint32_t)((mw + mi * 16 + arow) * TSTR + k0 + acol) * 2;
                ldm_x4(ah, base + aoff);
                #pragma unroll
                for (int p = 0; p < 2; ++p) {
                    mma_f16(acc[mi][2 * p],     ah, &bb[p][0]);
                    mma_f16(acc[mi][2 * p + 1], ah, &bb[p][2]);
                }
            }
        }
    }

    const int g = lane >> 2, tq = lane & 3;
    #pragma unroll
    for (int mi = 0; mi < 4; ++mi) {
        const int row0 = bm0 + mw + mi * 16 + g;
        #pragma unroll
        for (int ni = 0; ni < 4; ++ni) {
            const int col = bn0 + nw + ni * 8 + tq * 2;
            const float b0 = __ldg(&bias[col]), b1 = __ldg(&bias[col + 1]);
            float2 o0, o1;
            o0.x = fmaxf(acc[mi][ni][0] + b0, 0.f);
            o0.y = fmaxf(acc[mi][ni][1] + b1, 0.f);
            o1.x = fmaxf(acc[mi][ni][2] + b0, 0.f);
            o1.y = fmaxf(acc[mi][ni][3] + b1, 0.f);
            __stcs(reinterpret_cast<float2*>(&Cg[(size_t)row0 * N + col]), o0);
            __stcs(reinterpret_cast<float2*>(&Cg[(size_t)(row0 + 8) * N + col]), o1);
        }
    }
}

// =============================================================================
// Fused flash attention — 2 CTAs/SM; ex2 softmax; single barrier per kv-chunk;
// Q pre-scaled by scale*log2e in gemm_in.
// =============================================================================
constexpr int QSTR = 136;
constexpr int KSTR = 136;
constexpr int Q_HLV = 128 * QSTR;
constexpr int KV_TILE = 64 * KSTR;
constexpr int KV_STAGE = 2 * KV_TILE;
constexpr int ATT_SMEM = (Q_HLV + 2 * KV_STAGE) * 2;   // 104448 B

__global__ __launch_bounds__(256, 2)
void fused_attn(const __half* __restrict__ Ta0, const __half* __restrict__ Tb0,
                __half* __restrict__ U0,
                const __half* __restrict__ Ta1, const __half* __restrict__ Tb1,
                __half* __restrict__ U1)
{
    extern __shared__ __half sm[];
    const uint32_t smb = smem_u32(sm);
    const int tid = threadIdx.x, wid = tid >> 5, lane = tid & 31;
    const int z = blockIdx.z;
    const __half* Ta = z ? Ta1 : Ta0;
    const __half* Tb = z ? Tb1 : Tb0;
    __half* U = z ? U1 : U0;

    const int bz = blockIdx.y, b = bz >> 3, h = bz & 7;
    const int n0 = blockIdx.x * 128;
    const int wrow = wid * 16;

    const size_t qbase = (size_t)(b * CN + n0) * C3D + CD + h * CHD;
    const size_t kbase = (size_t)b * CN * C3D + h * CHD;
    const size_t vbase = (size_t)b * CN * C3D + 2 * CD + h * CHD;

    auto load_q = [&]() {
        #pragma unroll
        for (int i = 0; i < 8; ++i) {
            const int idx = tid + i * 256;
            const int r = idx >> 4, c = (idx & 15) * 8;
            cp_async16(smb + (uint32_t)(r * QSTR + c) * 2,
                       Ta + qbase + (size_t)r * C3D + c);
        }
        cp_commit();
    };
    auto load_kv = [&](int mc, int buf) {
        const int m0 = mc * 64;
        const uint32_t base = smb + (uint32_t)(Q_HLV + buf * KV_STAGE) * 2;
        const __half* kp = Tb + kbase + (size_t)m0 * C3D;
        const __half* vp = Tb + vbase + (size_t)m0 * C3D;
        #pragma unroll
        for (int i = 0; i < 4; ++i) {
            const int idx = tid + i * 256;
            const int r = idx >> 4, c = (idx & 15) * 8;
            const uint32_t doff = (uint32_t)(r * KSTR + c) * 2;
            cp_async16(base + doff,               kp + (size_t)r * C3D + c);
            cp_async16(base + KV_TILE * 2 + doff, vp + (size_t)r * C3D + c);
        }
        cp_commit();
    };

    load_q();
    load_kv(0, 0);

    const int arow = lane & 15, acol = (lane >> 4) * 8;
    const uint32_t q_addr0 = smb + (uint32_t)((wrow + arow) * QSTR + acol) * 2;

    const int g = lane >> 2, tq = lane & 3;
    const int bq_row = (lane & 7) + ((lane >> 4) & 1) * 8;
    const int bq_col = ((lane >> 3) & 1) * 8;
    const int vq_row = lane & 15;
    const int vq_col = ((lane >> 4) & 1) * 8;

    float m0s = -1e30f, m1s = -1e30f, l0s = 0.f, l1s = 0.f;
    float o[16][4] = {};

    for (int mc = 0; mc < 8; ++mc) {
        const int buf = mc & 1;
        cp_wait<0>();
        __syncthreads();
        if (mc + 1 < 8) load_kv(mc + 1, buf ^ 1);

        const uint32_t base = smb + (uint32_t)(Q_HLV + buf * KV_STAGE) * 2;

        float s[8][4] = {};
        #pragma unroll
        for (int kf = 0; kf < 8; ++kf) {
            uint32_t qf[4];
            ldm_x4(qf, q_addr0 + (uint32_t)(kf * 16) * 2);
            #pragma unroll
            for (int p = 0; p < 4; ++p) {
                const uint32_t boff =
                    (uint32_t)((p * 16 + bq_row) * KSTR + kf * 16 + bq_col) * 2;
                uint32_t kk4[4];
                ldm_x4(kk4, base + boff);
                mma_f16(s[2 * p],     qf, &kk4[0]);
                mma_f16(s[2 * p + 1], qf, &kk4[2]);
            }
        }

        float mx0 = -1e30f, mx1 = -1e30f;
        #pragma unroll
        for (int nf = 0; nf < 8; ++nf) {
            mx0 = fmaxf(mx0, fmaxf(s[nf][0], s[nf][1]));
            mx1 = fmaxf(mx1, fmaxf(s[nf][2], s[nf][3]));
        }
        mx0 = fmaxf(mx0, __shfl_xor_sync(0xffffffffu, mx0, 1));
        mx0 = fmaxf(mx0, __shfl_xor_sync(0xffffffffu, mx0, 2));
        mx1 = fmaxf(mx1, __shfl_xor_sync(0xffffffffu, mx1, 1));
        mx1 = fmaxf(mx1, __shfl_xor_sync(0xffffffffu, mx1, 2));
        const float mn0 = fmaxf(m0s, mx0), mn1 = fmaxf(m1s, mx1);
        const float a0 = fexp2(m0s - mn0), a1 = fexp2(m1s - mn1);
        m0s = mn0; m1s = mn1;

        float rs0 = 0.f, rs1 = 0.f;
        __half2 pf[8][2];
        #pragma unroll
        for (int nf = 0; nf < 8; ++nf) {
            const float p0 = fexp2(s[nf][0] - mn0);
            const float p1 = fexp2(s[nf][1] - mn0);
            const float p2 = fexp2(s[nf][2] - mn1);
            const float p3 = fexp2(s[nf][3] - mn1);
            rs0 += p0 + p1; rs1 += p2 + p3;
            pf[nf][0] = __halves2half2(__float2half_rn(p0), __float2half_rn(p1));
            pf[nf][1] = __halves2half2(__float2half_rn(p2), __float2half_rn(p3));
        }
        rs0 += __shfl_xor_sync(0xffffffffu, rs0, 1);
        rs0 += __shfl_xor_sync(0xffffffffu, rs0, 2);
        rs1 += __shfl_xor_sync(0xffffffffu, rs1, 1);
        rs1 += __shfl_xor_sync(0xffffffffu, rs1, 2);
        l0s = l0s * a0 + rs0;
        l1s = l1s * a1 + rs1;

        #pragma unroll
        for (int nf2 = 0; nf2 < 16; ++nf2) {
            o[nf2][0] *= a0; o[nf2][1] *= a0;
            o[nf2][2] *= a1; o[nf2][3] *= a1;
        }

        #pragma unroll
        for (int kf2 = 0; kf2 < 4; ++kf2) {
            uint32_t pa[4];
            pa[0] = *reinterpret_cast<uint32_t*>(&pf[2 * kf2][0]);
            pa[1] = *reinterpret_cast<uint32_t*>(&pf[2 * kf2][1]);
            pa[2] = *reinterpret_cast<uint32_t*>(&pf[2 * kf2 + 1][0]);
            pa[3] = *reinterpret_cast<uint32_t*>(&pf[2 * kf2 + 1][1]);
            #pragma unroll
            for (int p = 0; p < 8; ++p) {
                const uint32_t boff =
                    (uint32_t)((kf2 * 16 + vq_row) * KSTR + p * 16 + vq_col) * 2;
                uint32_t vv4[4];
                ldm_x4_trans(vv4, base + KV_TILE * 2 + boff);
                mma_f16(o[2 * p],     pa, &vv4[0]);
                mma_f16(o[2 * p + 1], pa, &vv4[2]);
            }
        }
    }

    const float inv0 = 1.f / l0s, inv1 = 1.f / l1s;
    const int row0 = n0 + wrow + g;
    #pragma unroll
    for (int nf2 = 0; nf2 < 16; ++nf2) {
        const int col = h * CHD + nf2 * 8 + tq * 2;
        const size_t off0 = (size_t)(b * CN + row0) * CD + col;
        const size_t off1 = (size_t)(b * CN + row0 + 8) * CD + col;
        *reinterpret_cast<__half2*>(&U[off0]) =
            __halves2half2(__float2half_rn(o[nf2][0] * inv0), __float2half_rn(o[nf2][1] * inv0));
        *reinterpret_cast<__half2*>(&U[off1]) =
            __halves2half2(__float2half_rn(o[nf2][2] * inv1), __float2half_rn(o[nf2][3] * inv1));
    }
}

// =============================================================================
// fused prep: weight transposes (blocks [0, 10240)) + input fp16 conversion
// (blocks [10240, 12288): 1024 blocks x 2 modalities)
// =============================================================================
__global__ __launch_bounds__(256)
void prep_all(const float* __restrict__ Wv, const float* __restrict__ Wq,
              const float* __restrict__ Wvo, const float* __restrict__ Wqo,
              __half* __restrict__ Tv, __half* __restrict__ Tq,
              __half* __restrict__ Tvo, __half* __restrict__ Tqo,
              const float* __restrict__ xv, __half* __restrict__ hv,
              const float* __restrict__ xq, __half* __restrict__ hq,
              size_t nconv)
{
    const int bid = blockIdx.x;
    if (bid < 10240) {
        const float* W; __half* T; int K, N, local;
        if (bid < 3072)      { W = Wv;  T = Tv;  K = 1024; N = 3072; local = bid; }
        else if (bid < 6144) { W = Wq;  T = Tq;  K = 1024; N = 3072; local = bid - 3072; }
        else if (bid < 8192) { W = Wvo; T = Tvo; K = 2048; N = 1024; local = bid - 6144; }
        else                 { W = Wqo; T = Tqo; K = 2048; N = 1024; local = bid - 8192; }
        const int ntiles = N / 32;
        const int k0 = (local / ntiles) * 32, n0 = (local % ntiles) * 32;

        __shared__ float t[32][33];
        const int tx = threadIdx.x & 31, ty = threadIdx.x >> 5;
        for (int i = ty; i < 32; i += 8)
            t[i][tx] = W[(size_t)(k0 + i) * N + n0 + tx];
        __syncthreads();
        for (int i = ty; i < 32; i += 8)
            T[(size_t)(n0 + i) * K + k0 + tx] = __float2half_rn(t[tx][i]);
    } else {
        const int bid2 = bid - 10240;
        const int zz = bid2 >> 10;
        const int xb = bid2 & 1023;
        const float* x = zz ? xq : xv;
        __half* hh = zz ? hq : hv;
        const size_t stride = (size_t)1024 * 256 * 4;
        for (size_t i = ((size_t)xb * 256 + threadIdx.x) * 4; i < nconv; i += stride) {
            float4 v = *reinterpret_cast<const float4*>(x + i);
            *reinterpret_cast<__half2*>(hh + i) =
                __halves2half2(__float2half_rn(v.x), __float2half_rn(v.y));
            *reinterpret_cast<__half2*>(hh + i + 2) =
                __halves2half2(__float2half_rn(v.z), __float2half_rn(v.w));
        }
    }
}

// =============================================================================
// launch
// =============================================================================
extern "C" void kernel_launch(void* const* d_in, const int* in_sizes, int n_in,
                              void* d_out, int out_size)
{
    const float* v   = (const float*)d_in[0];
    const float* q   = (const float*)d_in[1];
    const float* Wv  = (const float*)d_in[2];
    const float* bv  = (const float*)d_in[3];
    const float* Wq  = (const float*)d_in[4];
    const float* bq  = (const float*)d_in[5];
    const float* Wvo = (const float*)d_in[6];
    const float* bvo = (const float*)d_in[7];
    const float* Wqo = (const float*)d_in[8];
    const float* bqo = (const float*)d_in[9];
    float* out = (float*)d_out;

    __half *vt, *qt, *vh, *qh, *vu, *qu, *Wvt, *Wqt, *Wvot, *Wqot;
    cudaGetSymbolAddress((void**)&vt, g_vt);   cudaGetSymbolAddress((void**)&qt, g_qt);
    cudaGetSymbolAddress((void**)&vh, g_vh);   cudaGetSymbolAddress((void**)&qh, g_qh);
    cudaGetSymbolAddress((void**)&vu, g_vu);   cudaGetSymbolAddress((void**)&qu, g_qu);
    cudaGetSymbolAddress((void**)&Wvt, g_Wvt); cudaGetSymbolAddress((void**)&Wqt, g_Wqt);
    cudaGetSymbolAddress((void**)&Wvot, g_Wvot); cudaGetSymbolAddress((void**)&Wqot, g_Wqot);

    cudaFuncSetAttribute(gemm_in,  cudaFuncAttributeMaxDynamicSharedMemorySize, GEMM_SMEM);
    cudaFuncSetAttribute(gemm_out, cudaFuncAttributeMaxDynamicSharedMemorySize, GEMM_SMEM);
    cudaFuncSetAttribute(fused_attn, cudaFuncAttributeMaxDynamicSharedMemorySize, ATT_SMEM);

    const dim3 t256(256);
    const size_t nVD = (size_t)CM * CD;
    const size_t half = (size_t)CM * CD;

    // launch 0: fused prep (weight transposes + fp16 input copies)
    prep_all<<<12288, t256>>>(Wv, Wq, Wvo, Wqo, Wvt, Wqt, Wvot, Wqot,
                              v, vh, q, qh, nVD);

    // launch 1: input transforms (both modalities); query slice pre-scaled
    gemm_in<<<dim3(C3D / 128, CM / 128, 2), t256, GEMM_SMEM>>>(
        vh, qh, Wvt, Wqt, bv, bq, vt, qt, CM, C3D, CD);

    // launch 2: fused attention, both directions
    fused_attn<<<dim3(CN / 128, CB * CH, 2), t256, ATT_SMEM>>>(
        vt, qt, vu, qt, vt, qu);

    // launch 3: output transforms (virtual concat), both modalities
    gemm_out<<<dim3(CD / 128, CM / 128, 2), t256, GEMM_SMEM>>>(
        vh, vu, qh, qu, CD, Wvot, Wqot, bvo, bqo, out, half, CM, CD, 2 * CD);
}